// round 4
// baseline (speedup 1.0000x reference)
#include <cuda_runtime.h>
#include <math.h>
#include <stdint.h>

// Problem constants
#define Bc    2
#define Sc    2048
#define Ec    2048
#define Hc    16
#define HDc   128
#define Mrows 4096     // B*S
#define QKV_N 6144     // 3*E
#define GK    2048     // K dim of both GEMMs

// Scratch (device globals: allocation-free per harness rules)
__device__ float g_qkv[(size_t)Mrows * QKV_N];   // ~100 MB
__device__ float g_attn[(size_t)Mrows * Ec];     // ~33 MB

// ---------------------------------------------------------------------------
// Shared helpers
// ---------------------------------------------------------------------------
__device__ __forceinline__ uint32_t f2tf32(float x) {
    uint32_t r;
    asm("cvt.rna.tf32.f32 %0, %1;" : "=r"(r) : "f"(x));
    return r;
}

__device__ __forceinline__ uint2 split_tf32(float x) {
    uint32_t hi = f2tf32(x);
    float lo_f = x - __uint_as_float(hi);
    uint32_t lo = f2tf32(lo_f);
    return make_uint2(hi, lo);
}

__device__ __forceinline__ void mma8(float* c,
                                     uint32_t a0, uint32_t a1, uint32_t a2, uint32_t a3,
                                     uint32_t b0, uint32_t b1) {
    asm volatile(
        "mma.sync.aligned.m16n8k8.row.col.f32.tf32.tf32.f32 "
        "{%0,%1,%2,%3}, {%4,%5,%6,%7}, {%8,%9}, {%0,%1,%2,%3};"
        : "+f"(c[0]), "+f"(c[1]), "+f"(c[2]), "+f"(c[3])
        : "r"(a0), "r"(a1), "r"(a2), "r"(a3), "r"(b0), "r"(b1));
}

// ---------------------------------------------------------------------------
// 3xTF32 tensor-core GEMM (mma.sync): C[M,N] = A[M,K] @ B[N,K]^T + bias[N]
// (unchanged from R2 — passing at 143 TF/s issued)
// ---------------------------------------------------------------------------
#define BKg 32
#define SPAD 36

__global__ __launch_bounds__(256)
void gemm_tf32x3(const float* __restrict__ A,
                 const float* __restrict__ Bw,
                 const float* __restrict__ bias,
                 float* __restrict__ C,
                 int Ndim)
{
    extern __shared__ uint2 sm2[];
    uint2* As = sm2;                 // [128][SPAD]
    uint2* Bs = sm2 + 128 * SPAD;    // [128][SPAD]

    const int tid   = threadIdx.x;
    const int lane  = tid & 31;
    const int wid   = tid >> 5;
    const int m_off = (wid & 1) << 6;
    const int n_off = (wid >> 1) << 5;
    const int bm    = blockIdx.y << 7;
    const int bn    = blockIdx.x << 7;

    const int row_base = tid >> 3;
    const int col4     = (tid & 7) << 2;

    float c[4][4][4];
#pragma unroll
    for (int mt = 0; mt < 4; mt++)
#pragma unroll
        for (int nt = 0; nt < 4; nt++)
#pragma unroll
            for (int e = 0; e < 4; e++) c[mt][nt][e] = 0.f;

    float4 pa[4], pb[4];
#pragma unroll
    for (int i = 0; i < 4; i++) {
        int r = row_base + 32 * i;
        pa[i] = *(const float4*)&A [(size_t)(bm + r) * GK + col4];
        pb[i] = *(const float4*)&Bw[(size_t)(bn + r) * GK + col4];
    }

    const int nsteps = GK / BKg;
    for (int step = 0; step < nsteps; step++) {
        __syncthreads();
#pragma unroll
        for (int i = 0; i < 4; i++) {
            int r = row_base + 32 * i;
            float av[4] = {pa[i].x, pa[i].y, pa[i].z, pa[i].w};
            float bv[4] = {pb[i].x, pb[i].y, pb[i].z, pb[i].w};
            uint2 ah[4], bh[4];
#pragma unroll
            for (int j = 0; j < 4; j++) { ah[j] = split_tf32(av[j]); bh[j] = split_tf32(bv[j]); }
            *(uint4*)&As[r * SPAD + col4    ] = make_uint4(ah[0].x, ah[0].y, ah[1].x, ah[1].y);
            *(uint4*)&As[r * SPAD + col4 + 2] = make_uint4(ah[2].x, ah[2].y, ah[3].x, ah[3].y);
            *(uint4*)&Bs[r * SPAD + col4    ] = make_uint4(bh[0].x, bh[0].y, bh[1].x, bh[1].y);
            *(uint4*)&Bs[r * SPAD + col4 + 2] = make_uint4(bh[2].x, bh[2].y, bh[3].x, bh[3].y);
        }
        __syncthreads();

        if (step + 1 < nsteps) {
            int k0 = (step + 1) * BKg;
#pragma unroll
            for (int i = 0; i < 4; i++) {
                int r = row_base + 32 * i;
                pa[i] = *(const float4*)&A [(size_t)(bm + r) * GK + k0 + col4];
                pb[i] = *(const float4*)&Bw[(size_t)(bn + r) * GK + k0 + col4];
            }
        }

#pragma unroll
        for (int kk = 0; kk < 4; kk++) {
            const int kc = (kk << 3) + (lane & 3);
            uint2 a[4][4];
#pragma unroll
            for (int mt = 0; mt < 4; mt++) {
                int r0 = m_off + mt * 16 + (lane >> 2);
                a[mt][0] = As[r0 * SPAD + kc];
                a[mt][1] = As[(r0 + 8) * SPAD + kc];
                a[mt][2] = As[r0 * SPAD + kc + 4];
                a[mt][3] = As[(r0 + 8) * SPAD + kc + 4];
            }
            uint2 b[4][2];
#pragma unroll
            for (int nt = 0; nt < 4; nt++) {
                int n0 = n_off + nt * 8 + (lane >> 2);
                b[nt][0] = Bs[n0 * SPAD + kc];
                b[nt][1] = Bs[n0 * SPAD + kc + 4];
            }
#pragma unroll
            for (int mt = 0; mt < 4; mt++)
#pragma unroll
                for (int nt = 0; nt < 4; nt++) {
                    mma8(c[mt][nt], a[mt][0].x, a[mt][1].x, a[mt][2].x, a[mt][3].x,
                                    b[nt][0].x, b[nt][1].x);
                    mma8(c[mt][nt], a[mt][0].x, a[mt][1].x, a[mt][2].x, a[mt][3].x,
                                    b[nt][0].y, b[nt][1].y);
                    mma8(c[mt][nt], a[mt][0].y, a[mt][1].y, a[mt][2].y, a[mt][3].y,
                                    b[nt][0].x, b[nt][1].x);
                }
        }
    }

#pragma unroll
    for (int mt = 0; mt < 4; mt++) {
        int r0 = bm + m_off + mt * 16 + (lane >> 2);
#pragma unroll
        for (int nt = 0; nt < 4; nt++) {
            int col = bn + n_off + nt * 8 + ((lane & 3) << 1);
            float b0 = bias[col], b1 = bias[col + 1];
            *(float2*)&C[(size_t)r0 * Ndim + col] =
                make_float2(c[mt][nt][0] + b0, c[mt][nt][1] + b1);
            *(float2*)&C[(size_t)(r0 + 8) * Ndim + col] =
                make_float2(c[mt][nt][2] + b0, c[mt][nt][3] + b1);
        }
    }
}

// ---------------------------------------------------------------------------
// Flash attention on mma.sync tf32 (3xTF32 for QK^T and PV).
// CTA: 64 q-rows, K tiles of 32, 256 threads (8 warps).
// Smem (u32 units):
//   Qhi 0, Qlo 8448, Khi 16896, Klo 21120, Vs 25344 (f32, stride 136),
//   Ps 29696 (f32, stride 36), Phi 32000, Plo 34304,
//   m 36608, l 36672, alpha 36736; total 36800 u32 = 147200 B.
// ---------------------------------------------------------------------------
#define FQ 64
#define FK 32
#define QSTR 132
#define VSTR 136
#define PSTR 36
#define FL_SMEM_U32 36800

__global__ __launch_bounds__(256)
void flash_mma()
{
    extern __shared__ uint32_t sm[];
    uint32_t* Qhi = sm;
    uint32_t* Qlo = sm + 8448;
    uint32_t* Khi = sm + 16896;
    uint32_t* Klo = sm + 21120;
    float*    Vs  = (float*)(sm + 25344);
    float*    Ps  = (float*)(sm + 29696);
    uint32_t* Phi = sm + 32000;
    uint32_t* Plo = sm + 34304;
    float*    m_s  = (float*)(sm + 36608);
    float*    l_s  = (float*)(sm + 36672);
    float*    al_s = (float*)(sm + 36736);

    const int tid = threadIdx.x, lane = tid & 31, w = tid >> 5;
    const int b = blockIdx.z, h = blockIdx.y;
    const int q0 = blockIdx.x << 6;

    // ---- Load Q (64 x 128) and convert to tf32 hi/lo planes ----
    {
        int row = tid >> 2;
        int c0  = (tid & 3) << 5;
        const float* qp = &g_qkv[((size_t)(b*Sc + q0 + row)) * QKV_N + h*384 + c0];
#pragma unroll
        for (int j = 0; j < 8; j++) {
            float4 v = *(const float4*)(qp + 4*j);
            uint4 hi, lo;
            uint2 s;
            s = split_tf32(v.x); hi.x = s.x; lo.x = s.y;
            s = split_tf32(v.y); hi.y = s.x; lo.y = s.y;
            s = split_tf32(v.z); hi.z = s.x; lo.z = s.y;
            s = split_tf32(v.w); hi.w = s.x; lo.w = s.y;
            *(uint4*)&Qhi[row*QSTR + c0 + 4*j] = hi;
            *(uint4*)&Qlo[row*QSTR + c0 + 4*j] = lo;
        }
    }
    if (tid < FQ) { m_s[tid] = -INFINITY; l_s[tid] = 0.f; }

    // ---- Prefetch K/V tile 0 into registers ----
    const int krow = tid >> 3;          // 0..31
    const int kc0  = (tid & 7) << 4;    // 0,16,...,112
    float4 rk[4], rv[4];
    {
        const float* kp = &g_qkv[((size_t)(b*Sc + krow)) * QKV_N + h*384 + 128 + kc0];
#pragma unroll
        for (int j = 0; j < 4; j++) {
            rk[j] = *(const float4*)(kp + 4*j);
            rv[j] = *(const float4*)(kp + 128 + 4*j);
        }
    }

    float o[2][4][4];
#pragma unroll
    for (int mt = 0; mt < 2; mt++)
#pragma unroll
        for (int nt = 0; nt < 4; nt++)
#pragma unroll
            for (int e = 0; e < 4; e++) o[mt][nt][e] = 0.f;

    const int qk_m0 = (w & 3) << 4;    // 0,16,32,48
    const int qk_n0 = (w >> 2) << 4;   // 0 or 16 (two n-tiles of 8)
    const int pv_m0 = (w & 1) << 5;    // 0 or 32
    const int pv_n0 = (w >> 1) << 5;   // 0,32,64,96
    const float scale = 11.3137084989847604f;  // HD**0.5 (reference MULTIPLIES)

#pragma unroll 1
    for (int kt = 0; kt < Sc / FK; kt++) {
        __syncthreads();   // Vs/Phi/Plo free (previous PV done); Q/state visible

        // store K (hi/lo) + V (fp32) tile
#pragma unroll
        for (int j = 0; j < 4; j++) {
            float4 kv = rk[j];
            uint4 hi, lo;
            uint2 s;
            s = split_tf32(kv.x); hi.x = s.x; lo.x = s.y;
            s = split_tf32(kv.y); hi.y = s.x; lo.y = s.y;
            s = split_tf32(kv.z); hi.z = s.x; lo.z = s.y;
            s = split_tf32(kv.w); hi.w = s.x; lo.w = s.y;
            *(uint4*)&Khi[krow*QSTR + kc0 + 4*j] = hi;
            *(uint4*)&Klo[krow*QSTR + kc0 + 4*j] = lo;
            *(float4*)&Vs[krow*VSTR + kc0 + 4*j] = rv[j];
        }
        __syncthreads();

        // prefetch next tile (overlaps mma below)
        if (kt + 1 < Sc / FK) {
            const float* kp = &g_qkv[((size_t)(b*Sc + (kt+1)*FK + krow)) * QKV_N
                                     + h*384 + 128 + kc0];
#pragma unroll
            for (int j = 0; j < 4; j++) {
                rk[j] = *(const float4*)(kp + 4*j);
                rv[j] = *(const float4*)(kp + 128 + 4*j);
            }
        }

        // ---- S = Q @ K^T via 3xTF32 mma ----
        float sf[2][4];
#pragma unroll
        for (int j = 0; j < 2; j++)
#pragma unroll
            for (int e = 0; e < 4; e++) sf[j][e] = 0.f;

#pragma unroll
        for (int kk = 0; kk < 16; kk++) {
            const int kc = (kk << 3) + (lane & 3);
            const int ar = qk_m0 + (lane >> 2);
            uint32_t ah0 = Qhi[ar*QSTR + kc],       ah1 = Qhi[(ar+8)*QSTR + kc];
            uint32_t ah2 = Qhi[ar*QSTR + kc + 4],   ah3 = Qhi[(ar+8)*QSTR + kc + 4];
            uint32_t al0 = Qlo[ar*QSTR + kc],       al1 = Qlo[(ar+8)*QSTR + kc];
            uint32_t al2 = Qlo[ar*QSTR + kc + 4],   al3 = Qlo[(ar+8)*QSTR + kc + 4];
#pragma unroll
            for (int j = 0; j < 2; j++) {
                int n0 = qk_n0 + (j << 3) + (lane >> 2);
                uint32_t bh0 = Khi[n0*QSTR + kc], bh1 = Khi[n0*QSTR + kc + 4];
                uint32_t bl0 = Klo[n0*QSTR + kc], bl1 = Klo[n0*QSTR + kc + 4];
                mma8(sf[j], ah0, ah1, ah2, ah3, bh0, bh1);
                mma8(sf[j], ah0, ah1, ah2, ah3, bl0, bl1);
                mma8(sf[j], al0, al1, al2, al3, bh0, bh1);
            }
        }
        {
            int r0 = qk_m0 + (lane >> 2);
            int cc = (lane & 3) << 1;
#pragma unroll
            for (int j = 0; j < 2; j++) {
                int col = qk_n0 + (j << 3) + cc;
                *(float2*)&Ps[r0*PSTR + col]     = make_float2(sf[j][0]*scale, sf[j][1]*scale);
                *(float2*)&Ps[(r0+8)*PSTR + col] = make_float2(sf[j][2]*scale, sf[j][3]*scale);
            }
        }
        __syncthreads();

        // ---- online softmax: warp w handles rows 8w..8w+7 (lane = col) ----
#pragma unroll 1
        for (int rr = 0; rr < 8; rr++) {
            int r = (w << 3) + rr;
            float s = Ps[r*PSTR + lane];
            float mx = s;
#pragma unroll
            for (int off = 16; off > 0; off >>= 1)
                mx = fmaxf(mx, __shfl_xor_sync(0xffffffffu, mx, off));
            float mo = m_s[r];
            float mn = fmaxf(mo, mx);
            float p = __expf(s - mn);
            float psum = p;
#pragma unroll
            for (int off = 16; off > 0; off >>= 1)
                psum += __shfl_xor_sync(0xffffffffu, psum, off);
            uint32_t phi = f2tf32(p);
            Phi[r*PSTR + lane] = phi;
            Plo[r*PSTR + lane] = f2tf32(p - __uint_as_float(phi));
            if (lane == 0) {
                float al = (mo == -INFINITY) ? 0.f : __expf(mo - mn);
                al_s[r] = al;
                l_s[r]  = l_s[r]*al + psum;
                m_s[r]  = mn;
            }
        }
        __syncthreads();

        // ---- O = O*alpha + P @ V via 3xTF32 mma ----
#pragma unroll
        for (int mt = 0; mt < 2; mt++) {
            float a0 = al_s[pv_m0 + (mt << 4) + (lane >> 2)];
            float a1 = al_s[pv_m0 + (mt << 4) + 8 + (lane >> 2)];
#pragma unroll
            for (int nt = 0; nt < 4; nt++) {
                o[mt][nt][0] *= a0; o[mt][nt][1] *= a0;
                o[mt][nt][2] *= a1; o[mt][nt][3] *= a1;
            }
        }
#pragma unroll
        for (int kk = 0; kk < 4; kk++) {
            const int kc = (kk << 3) + (lane & 3);
            uint32_t ah[2][4], alr[2][4];
#pragma unroll
            for (int mt = 0; mt < 2; mt++) {
                int r0 = pv_m0 + (mt << 4) + (lane >> 2);
                ah[mt][0]  = Phi[r0*PSTR + kc];     ah[mt][1]  = Phi[(r0+8)*PSTR + kc];
                ah[mt][2]  = Phi[r0*PSTR + kc + 4]; ah[mt][3]  = Phi[(r0+8)*PSTR + kc + 4];
                alr[mt][0] = Plo[r0*PSTR + kc];     alr[mt][1] = Plo[(r0+8)*PSTR + kc];
                alr[mt][2] = Plo[r0*PSTR + kc + 4]; alr[mt][3] = Plo[(r0+8)*PSTR + kc + 4];
            }
#pragma unroll
            for (int nt = 0; nt < 4; nt++) {
                int n0 = pv_n0 + (nt << 3) + (lane >> 2);
                float v0 = Vs[kc*VSTR + n0];
                float v1 = Vs[(kc + 4)*VSTR + n0];
                uint32_t vh0 = f2tf32(v0), vl0 = f2tf32(v0 - __uint_as_float(vh0));
                uint32_t vh1 = f2tf32(v1), vl1 = f2tf32(v1 - __uint_as_float(vh1));
#pragma unroll
                for (int mt = 0; mt < 2; mt++) {
                    mma8(o[mt][nt], ah[mt][0],  ah[mt][1],  ah[mt][2],  ah[mt][3],  vh0, vh1);
                    mma8(o[mt][nt], ah[mt][0],  ah[mt][1],  ah[mt][2],  ah[mt][3],  vl0, vl1);
                    mma8(o[mt][nt], alr[mt][0], alr[mt][1], alr[mt][2], alr[mt][3], vh0, vh1);
                }
            }
        }
    }

    // ---- epilogue: normalize by l, scatter to (b, s, h*HD + d) ----
#pragma unroll
    for (int mt = 0; mt < 2; mt++) {
        int r0 = pv_m0 + (mt << 4) + (lane >> 2);
        float i0 = 1.f / l_s[r0];
        float i1 = 1.f / l_s[r0 + 8];
        size_t g0 = ((size_t)(b*Sc + q0 + r0)) * Ec + h*HDc;
        size_t g1 = ((size_t)(b*Sc + q0 + r0 + 8)) * Ec + h*HDc;
#pragma unroll
        for (int nt = 0; nt < 4; nt++) {
            int col = pv_n0 + (nt << 3) + ((lane & 3) << 1);
            *(float2*)&g_attn[g0 + col] = make_float2(o[mt][nt][0]*i0, o[mt][nt][1]*i0);
            *(float2*)&g_attn[g1 + col] = make_float2(o[mt][nt][2]*i1, o[mt][nt][3]*i1);
        }
    }
}

// ---------------------------------------------------------------------------
extern "C" void kernel_launch(void* const* d_in, const int* in_sizes, int n_in,
                              void* d_out, int out_size)
{
    const float* query = (const float*)d_in[0];
    const float* Wqkv  = (const float*)d_in[3];
    const float* bqkv  = (const float*)d_in[4];
    const float* Wproj = (const float*)d_in[5];
    const float* bproj = (const float*)d_in[6];
    float* out = (float*)d_out;

    float *qkvp = nullptr, *attnp = nullptr;
    cudaGetSymbolAddress((void**)&qkvp,  g_qkv);
    cudaGetSymbolAddress((void**)&attnp, g_attn);

    const int gemm_smem = 2 * 128 * SPAD * (int)sizeof(uint2);  // 73728
    cudaFuncSetAttribute(gemm_tf32x3,
                         cudaFuncAttributeMaxDynamicSharedMemorySize, gemm_smem);

    // 1) qkv = query @ Wqkv^T + bqkv
    gemm_tf32x3<<<dim3(QKV_N/128, Mrows/128), 256, gemm_smem>>>(
        query, Wqkv, bqkv, qkvp, QKV_N);

    // 2) flash attention (mma.sync tf32 x3) -> g_attn
    const int fl_smem = FL_SMEM_U32 * (int)sizeof(uint32_t);  // 147200
    cudaFuncSetAttribute(flash_mma,
                         cudaFuncAttributeMaxDynamicSharedMemorySize, fl_smem);
    flash_mma<<<dim3(Sc/FQ, Hc, Bc), 256, fl_smem>>>();

    // 3) out = attn @ Wproj^T + bproj
    gemm_tf32x3<<<dim3(Ec/128, Mrows/128), 256, gemm_smem>>>(
        attnp, Wproj, bproj, out, Ec);
}

// round 5
// speedup vs baseline: 1.0270x; 1.0270x over previous
#include <cuda_runtime.h>
#include <math.h>
#include <stdint.h>

// Problem constants
#define Bc    2
#define Sc    2048
#define Ec    2048
#define Hc    16
#define HDc   128
#define Mrows 4096     // B*S
#define QKV_N 6144     // 3*E
#define GK    2048     // K dim of both GEMMs

// Scratch (device globals: allocation-free per harness rules)
__device__ float g_qkv[(size_t)Mrows * QKV_N];        // ~100 MB
__device__ float g_attn[(size_t)Mrows * Ec];          // ~33 MB
__device__ uint32_t g_ahi[(size_t)Mrows * GK];        // 32 MB (A hi plane)
__device__ uint32_t g_alo[(size_t)Mrows * GK];        // 32 MB
__device__ uint32_t g_bhi[(size_t)QKV_N * GK];        // 48 MB (B hi plane)
__device__ uint32_t g_blo[(size_t)QKV_N * GK];        // 48 MB

// ---------------------------------------------------------------------------
// Helpers
// ---------------------------------------------------------------------------
__device__ __forceinline__ uint32_t f2tf32(float x) {
    uint32_t r;
    asm("cvt.rna.tf32.f32 %0, %1;" : "=r"(r) : "f"(x));
    return r;
}

__device__ __forceinline__ void mma8(float* c,
                                     uint32_t a0, uint32_t a1, uint32_t a2, uint32_t a3,
                                     uint32_t b0, uint32_t b1) {
    asm volatile(
        "mma.sync.aligned.m16n8k8.row.col.f32.tf32.tf32.f32 "
        "{%0,%1,%2,%3}, {%4,%5,%6,%7}, {%8,%9}, {%0,%1,%2,%3};"
        : "+f"(c[0]), "+f"(c[1]), "+f"(c[2]), "+f"(c[3])
        : "r"(a0), "r"(a1), "r"(a2), "r"(a3), "r"(b0), "r"(b1));
}

// ---------------------------------------------------------------------------
// Pre-pass: split fp32 array into tf32 hi/lo planes (memory-bound)
// ---------------------------------------------------------------------------
__global__ __launch_bounds__(256)
void split_planes(const float* __restrict__ X,
                  uint32_t* __restrict__ Hi,
                  uint32_t* __restrict__ Lo,
                  size_t n4)
{
    size_t i = ((size_t)blockIdx.x * blockDim.x + threadIdx.x) << 2;
    if (i < (n4 << 2)) {
        float4 v = *(const float4*)&X[i];
        uint4 hi, lo;
        hi.x = f2tf32(v.x); lo.x = f2tf32(v.x - __uint_as_float(hi.x));
        hi.y = f2tf32(v.y); lo.y = f2tf32(v.y - __uint_as_float(hi.y));
        hi.z = f2tf32(v.z); lo.z = f2tf32(v.z - __uint_as_float(hi.z));
        hi.w = f2tf32(v.w); lo.w = f2tf32(v.w - __uint_as_float(hi.w));
        *(uint4*)&Hi[i] = hi;
        *(uint4*)&Lo[i] = lo;
    }
}

// ---------------------------------------------------------------------------
// 3xTF32 tensor-core GEMM from pre-split planes:
// C[M,N] = A[M,K] @ B[N,K]^T + bias[N], K-major operands.
// 128x128 tile, BK=32, 256 threads, warp tile 64x32. No cvt in mainloop.
// ---------------------------------------------------------------------------
#define BKg 32
#define SPAD 36          // row stride in uint2

__global__ __launch_bounds__(256)
void gemm_planes(const uint32_t* __restrict__ Ahi,
                 const uint32_t* __restrict__ Alo,
                 const uint32_t* __restrict__ Bhi,
                 const uint32_t* __restrict__ Blo,
                 const float* __restrict__ bias,
                 float* __restrict__ C,
                 int Ndim)
{
    extern __shared__ uint2 sm2[];
    uint2* As = sm2;                 // [128][SPAD]  {hi,lo}
    uint2* Bs = sm2 + 128 * SPAD;

    const int tid   = threadIdx.x;
    const int lane  = tid & 31;
    const int wid   = tid >> 5;
    const int m_off = (wid & 1) << 6;
    const int n_off = (wid >> 1) << 5;
    const int bm    = blockIdx.y << 7;
    const int bn    = blockIdx.x << 7;

    const int row_base = tid >> 3;        // 0..31
    const int col4     = (tid & 7) << 2;  // 0..28

    float c[4][4][4];
#pragma unroll
    for (int mt = 0; mt < 4; mt++)
#pragma unroll
        for (int nt = 0; nt < 4; nt++)
#pragma unroll
            for (int e = 0; e < 4; e++) c[mt][nt][e] = 0.f;

    uint4 pah[4], pal[4], pbh[4], pbl[4];
#pragma unroll
    for (int i = 0; i < 4; i++) {
        size_t ra = (size_t)(bm + row_base + 32 * i) * GK + col4;
        size_t rb = (size_t)(bn + row_base + 32 * i) * GK + col4;
        pah[i] = *(const uint4*)&Ahi[ra];
        pal[i] = *(const uint4*)&Alo[ra];
        pbh[i] = *(const uint4*)&Bhi[rb];
        pbl[i] = *(const uint4*)&Blo[rb];
    }

    const int nsteps = GK / BKg;
    for (int step = 0; step < nsteps; step++) {
        __syncthreads();
#pragma unroll
        for (int i = 0; i < 4; i++) {
            int r = row_base + 32 * i;
            *(uint4*)&As[r * SPAD + col4    ] = make_uint4(pah[i].x, pal[i].x, pah[i].y, pal[i].y);
            *(uint4*)&As[r * SPAD + col4 + 2] = make_uint4(pah[i].z, pal[i].z, pah[i].w, pal[i].w);
            *(uint4*)&Bs[r * SPAD + col4    ] = make_uint4(pbh[i].x, pbl[i].x, pbh[i].y, pbl[i].y);
            *(uint4*)&Bs[r * SPAD + col4 + 2] = make_uint4(pbh[i].z, pbl[i].z, pbh[i].w, pbl[i].w);
        }
        __syncthreads();

        if (step + 1 < nsteps) {
            int k0 = (step + 1) * BKg;
#pragma unroll
            for (int i = 0; i < 4; i++) {
                size_t ra = (size_t)(bm + row_base + 32 * i) * GK + k0 + col4;
                size_t rb = (size_t)(bn + row_base + 32 * i) * GK + k0 + col4;
                pah[i] = *(const uint4*)&Ahi[ra];
                pal[i] = *(const uint4*)&Alo[ra];
                pbh[i] = *(const uint4*)&Bhi[rb];
                pbl[i] = *(const uint4*)&Blo[rb];
            }
        }

#pragma unroll
        for (int kk = 0; kk < 4; kk++) {
            const int kc = (kk << 3) + (lane & 3);
            uint2 a[4][4];
#pragma unroll
            for (int mt = 0; mt < 4; mt++) {
                int r0 = m_off + mt * 16 + (lane >> 2);
                a[mt][0] = As[r0 * SPAD + kc];
                a[mt][1] = As[(r0 + 8) * SPAD + kc];
                a[mt][2] = As[r0 * SPAD + kc + 4];
                a[mt][3] = As[(r0 + 8) * SPAD + kc + 4];
            }
            uint2 b[4][2];
#pragma unroll
            for (int nt = 0; nt < 4; nt++) {
                int n0 = n_off + nt * 8 + (lane >> 2);
                b[nt][0] = Bs[n0 * SPAD + kc];
                b[nt][1] = Bs[n0 * SPAD + kc + 4];
            }
#pragma unroll
            for (int mt = 0; mt < 4; mt++)
#pragma unroll
                for (int nt = 0; nt < 4; nt++) {
                    mma8(c[mt][nt], a[mt][0].x, a[mt][1].x, a[mt][2].x, a[mt][3].x,
                                    b[nt][0].x, b[nt][1].x);
                    mma8(c[mt][nt], a[mt][0].x, a[mt][1].x, a[mt][2].x, a[mt][3].x,
                                    b[nt][0].y, b[nt][1].y);
                    mma8(c[mt][nt], a[mt][0].y, a[mt][1].y, a[mt][2].y, a[mt][3].y,
                                    b[nt][0].x, b[nt][1].x);
                }
        }
    }

#pragma unroll
    for (int mt = 0; mt < 4; mt++) {
        int r0 = bm + m_off + mt * 16 + (lane >> 2);
#pragma unroll
        for (int nt = 0; nt < 4; nt++) {
            int col = bn + n_off + nt * 8 + ((lane & 3) << 1);
            float b0 = bias[col], b1 = bias[col + 1];
            *(float2*)&C[(size_t)r0 * Ndim + col] =
                make_float2(c[mt][nt][0] + b0, c[mt][nt][1] + b1);
            *(float2*)&C[(size_t)(r0 + 8) * Ndim + col] =
                make_float2(c[mt][nt][2] + b0, c[mt][nt][3] + b1);
        }
    }
}

// ---------------------------------------------------------------------------
// Flash attention, fp32 SIMT (proven R1 kernel, ~2.4 ms)
// ---------------------------------------------------------------------------
#define SQt 128
#define SKt 64
#define DP  132

__global__ __launch_bounds__(256)
void flash_fp32()
{
    extern __shared__ float smf[];
    float* Qs   = smf;
    float* Ks   = Qs  + SQt*DP;
    float* Vs   = Ks  + SKt*DP;
    float* Ps   = Vs  + SKt*DP;
    float* m_s  = Ps  + SQt*SKt;
    float* l_s  = m_s + SQt;
    float* al_s = l_s + SQt;

    const int tid  = threadIdx.x;
    const int lane = tid & 31, wid = tid >> 5;
    const int ty   = tid >> 4, tx  = tid & 15;
    const int b = blockIdx.z, h = blockIdx.y;
    const int q0 = blockIdx.x << 7;

    const size_t qbase = ((size_t)(b*Sc + q0)) * QKV_N + h*384;

#pragma unroll
    for (int i = 0; i < 16; i++) {
        int idx = tid + (i << 8);
        int r   = idx >> 5;
        int c4  = (idx & 31) << 2;
        *(float4*)&Qs[r*DP + c4] =
            *(const float4*)&g_qkv[qbase + (size_t)r*QKV_N + c4];
    }
    if (tid < SQt) { m_s[tid] = -INFINITY; l_s[tid] = 0.f; }

    float o[8][8];
#pragma unroll
    for (int i = 0; i < 8; i++)
#pragma unroll
        for (int c = 0; c < 8; c++) o[i][c] = 0.f;

    const float scale = 11.3137084989847604f;  // HD**0.5 (reference MULTIPLIES)

    for (int kt = 0; kt < Sc; kt += SKt) {
        __syncthreads();
        const size_t kbase = ((size_t)(b*Sc + kt)) * QKV_N + h*384;
#pragma unroll
        for (int i = 0; i < 8; i++) {
            int idx = tid + (i << 8);
            int r   = idx >> 5;
            int c4  = (idx & 31) << 2;
            *(float4*)&Ks[r*DP + c4] =
                *(const float4*)&g_qkv[kbase + (size_t)r*QKV_N + 128 + c4];
            *(float4*)&Vs[r*DP + c4] =
                *(const float4*)&g_qkv[kbase + (size_t)r*QKV_N + 256 + c4];
        }
        __syncthreads();

        float s[8][4];
#pragma unroll
        for (int i = 0; i < 8; i++)
#pragma unroll
            for (int c = 0; c < 4; c++) s[i][c] = 0.f;

#pragma unroll 8
        for (int d = 0; d < HDc; d += 4) {
            float4 kf[4];
#pragma unroll
            for (int c = 0; c < 4; c++)
                kf[c] = *(const float4*)&Ks[(tx + 16*c)*DP + d];
#pragma unroll
            for (int i = 0; i < 8; i++) {
                float4 qf = *(const float4*)&Qs[(8*ty + i)*DP + d];
#pragma unroll
                for (int c = 0; c < 4; c++)
                    s[i][c] += qf.x*kf[c].x + qf.y*kf[c].y
                             + qf.z*kf[c].z + qf.w*kf[c].w;
            }
        }
#pragma unroll
        for (int i = 0; i < 8; i++)
#pragma unroll
            for (int c = 0; c < 4; c++)
                Ps[(8*ty + i)*SKt + tx + 16*c] = s[i][c] * scale;
        __syncthreads();

#pragma unroll 1
        for (int rr = 0; rr < 16; rr++) {
            int r = wid*16 + rr;
            float s0 = Ps[r*SKt + lane];
            float s1 = Ps[r*SKt + 32 + lane];
            float mx = fmaxf(s0, s1);
#pragma unroll
            for (int off = 16; off > 0; off >>= 1)
                mx = fmaxf(mx, __shfl_xor_sync(0xffffffffu, mx, off));
            float mo = m_s[r];
            float mn = fmaxf(mo, mx);
            float p0 = __expf(s0 - mn);
            float p1 = __expf(s1 - mn);
            float ps = p0 + p1;
#pragma unroll
            for (int off = 16; off > 0; off >>= 1)
                ps += __shfl_xor_sync(0xffffffffu, ps, off);
            Ps[r*SKt + lane]      = p0;
            Ps[r*SKt + 32 + lane] = p1;
            if (lane == 0) {
                float al = (mo == -INFINITY) ? 0.f : __expf(mo - mn);
                al_s[r] = al;
                l_s[r]  = l_s[r]*al + ps;
                m_s[r]  = mn;
            }
        }
        __syncthreads();

        float al[8];
#pragma unroll
        for (int i = 0; i < 8; i++) al[i] = al_s[8*ty + i];
#pragma unroll
        for (int i = 0; i < 8; i++)
#pragma unroll
            for (int c = 0; c < 8; c++) o[i][c] *= al[i];

#pragma unroll 4
        for (int j = 0; j < SKt; j++) {
            float p[8], v[8];
#pragma unroll
            for (int i = 0; i < 8; i++) p[i] = Ps[(8*ty + i)*SKt + j];
#pragma unroll
            for (int c = 0; c < 8; c++) v[c] = Vs[j*DP + tx + 16*c];
#pragma unroll
            for (int i = 0; i < 8; i++)
#pragma unroll
                for (int c = 0; c < 8; c++)
                    o[i][c] += p[i]*v[c];
        }
    }

#pragma unroll
    for (int i = 0; i < 8; i++) {
        int r = 8*ty + i;
        float inv = 1.0f / l_s[r];
        size_t obase = ((size_t)(b*Sc + q0 + r)) * Ec + h*HDc;
#pragma unroll
        for (int c = 0; c < 8; c++)
            g_attn[obase + tx + 16*c] = o[i][c] * inv;
    }
}

// ---------------------------------------------------------------------------
extern "C" void kernel_launch(void* const* d_in, const int* in_sizes, int n_in,
                              void* d_out, int out_size)
{
    const float* query = (const float*)d_in[0];
    const float* Wqkv  = (const float*)d_in[3];
    const float* bqkv  = (const float*)d_in[4];
    const float* Wproj = (const float*)d_in[5];
    const float* bproj = (const float*)d_in[6];
    float* out = (float*)d_out;

    float *qkvp = nullptr, *attnp = nullptr;
    uint32_t *ahi, *alo, *bhi, *blo;
    cudaGetSymbolAddress((void**)&qkvp,  g_qkv);
    cudaGetSymbolAddress((void**)&attnp, g_attn);
    cudaGetSymbolAddress((void**)&ahi, g_ahi);
    cudaGetSymbolAddress((void**)&alo, g_alo);
    cudaGetSymbolAddress((void**)&bhi, g_bhi);
    cudaGetSymbolAddress((void**)&blo, g_blo);

    const int gemm_smem = 2 * 128 * SPAD * (int)sizeof(uint2);  // 73728
    cudaFuncSetAttribute(gemm_planes,
                         cudaFuncAttributeMaxDynamicSharedMemorySize, gemm_smem);

    const size_t nA = (size_t)Mrows * GK;   // 8M
    const size_t nB1 = (size_t)QKV_N * GK;  // 12M
    const size_t nB2 = (size_t)Ec * GK;     // 4M

    // 0) split query + Wqkv into tf32 planes
    split_planes<<<(int)(nA  / 4 / 256), 256>>>(query, ahi, alo, nA  / 4);
    split_planes<<<(int)(nB1 / 4 / 256), 256>>>(Wqkv,  bhi, blo, nB1 / 4);

    // 1) qkv = query @ Wqkv^T + bqkv
    gemm_planes<<<dim3(QKV_N/128, Mrows/128), 256, gemm_smem>>>(
        ahi, alo, bhi, blo, bqkv, qkvp, QKV_N);

    // 2) flash attention -> g_attn
    const int fl_smem = (SQt*DP + 2*SKt*DP + SQt*SKt + 3*SQt) * (int)sizeof(float);
    cudaFuncSetAttribute(flash_fp32,
                         cudaFuncAttributeMaxDynamicSharedMemorySize, fl_smem);
    flash_fp32<<<dim3(Sc/128, Hc, Bc), 256, fl_smem>>>();

    // 2b) split attn + Wproj into planes
    split_planes<<<(int)(nA  / 4 / 256), 256>>>(attnp, ahi, alo, nA  / 4);
    split_planes<<<(int)(nB2 / 4 / 256), 256>>>(Wproj, bhi, blo, nB2 / 4);

    // 3) out = attn @ Wproj^T + bproj
    gemm_planes<<<dim3(Ec/128, Mrows/128), 256, gemm_smem>>>(
        ahi, alo, bhi, blo, bproj, out, Ec);
}